// round 1
// baseline (speedup 1.0000x reference)
#include <cuda_runtime.h>
#include <cuda_bf16.h>

// Problem constants
#define B_   256
#define S_   512
#define H_   768
#define WDIM 25
#define NLAB 42
#define CIN  2354   // 2*H + 2*WDIM + H
#define MAXW 10

// GEMM1 tiling
#define BM 64
#define BN 64
#define BKT 32
#define KSPLIT 3
#define KCHUNK 785   // ceil(2354/3)

// Scratch (no cudaMalloc allowed)
__device__ float g_comb[B_ * CIN];                 // [256, 2354]
__device__ float g_part[KSPLIT * B_ * H_];         // split-K partials [3, 256, 768]

// ---------------------------------------------------------------------------
// Kernel 1: build combined feature vector
//   combined = [e1_repr(768) | e2_repr(768) | e1_w(25) | e2_w(25) | ctx(768)]
// one block per batch element, 256 threads
// ---------------------------------------------------------------------------
__global__ __launch_bounds__(256) void build_combined_kernel(
    const float* __restrict__ seq,      // [B,S,H]
    const int*   __restrict__ e1p,
    const int*   __restrict__ e2p,
    const int*   __restrict__ l1,
    const int*   __restrict__ l2,
    const float* __restrict__ wemb)     // [11, 25]
{
    int b = blockIdx.x;
    int t = threadIdx.x;

    int p1 = e1p[b];
    int p2 = e2p[b];

    const float* row1 = seq + ((size_t)b * S_ + p1) * H_;
    const float* row2 = seq + ((size_t)b * S_ + p2) * H_;
    float* out = g_comb + (size_t)b * CIN;

    // entity token reps
    #pragma unroll
    for (int h = t; h < H_; h += 256) {
        out[h]      = row1[h];
        out[H_ + h] = row2[h];
    }

    // width embeddings
    if (t < WDIM) {
        int w1 = min(l1[b], MAXW);
        out[2 * H_ + t] = wemb[w1 * WDIM + t];
    } else if (t >= 32 && t < 32 + WDIM) {
        int w2 = min(l2[b], MAXW);
        out[2 * H_ + WDIM + (t - 32)] = wemb[w2 * WDIM + (t - 32)];
    }

    // masked mean over positions strictly between p1 and p2
    int start = p1 + 1;
    int end   = p2;               // exclusive
    int cnt   = end - start;
    float inv = (cnt > 0) ? (1.0f / (float)cnt) : 0.0f;

    const float* base = seq + (size_t)b * S_ * H_;
    #pragma unroll
    for (int h = t; h < H_; h += 256) {
        float s = 0.0f;
        for (int p = start; p < end; p++) {
            s += base[(size_t)p * H_ + h];
        }
        out[2 * H_ + 2 * WDIM + h] = s * inv;   // inv==0 -> ctx==0 when span empty
    }
}

// ---------------------------------------------------------------------------
// Kernel 2: split-K GEMM1 partials:  part[ks] += comb[:, k0:k1] @ W1[k0:k1, :]
//   M=256, N=768, K=2354. grid = (12, 4, 3), block = 256. 64x64 tile, 4x4 micro.
// ---------------------------------------------------------------------------
__global__ __launch_bounds__(256, 1) void gemm1_kernel(
    const float* __restrict__ W1)   // [CIN, H]
{
    __shared__ float As[BKT][BM + 1];   // transposed A tile, padded (stride 65)
    __shared__ float Bs[BKT][BN];

    const int tid = threadIdx.x;
    const int bn = blockIdx.x;     // 0..11
    const int bm = blockIdx.y;     // 0..3
    const int ks = blockIdx.z;     // 0..2

    const int row0 = bm * BM;
    const int col0 = bn * BN;
    const int k0 = ks * KCHUNK;
    const int k1 = min(k0 + KCHUNK, CIN);

    const int ty = tid >> 4;       // 0..15 -> rows ty*4 .. ty*4+3
    const int tx = tid & 15;       // 0..15 -> cols tx*4 .. tx*4+3

    float acc[4][4] = {};

    const float* A = g_comb;

    for (int kt = k0; kt < k1; kt += BKT) {
        // --- load A tile 64x32, store transposed As[k][row] ---
        #pragma unroll
        for (int i = 0; i < 8; i++) {
            int e  = tid + i * 256;
            int r  = e >> 5;        // 0..63
            int kk = e & 31;
            int kg = kt + kk;
            As[kk][r] = (kg < k1) ? A[(size_t)(row0 + r) * CIN + kg] : 0.0f;
        }
        // --- load B tile 32x64 direct ---
        #pragma unroll
        for (int i = 0; i < 8; i++) {
            int e  = tid + i * 256;
            int kr = e >> 6;        // 0..31
            int c  = e & 63;
            int kg = kt + kr;
            Bs[kr][c] = (kg < k1) ? W1[(size_t)kg * H_ + col0 + c] : 0.0f;
        }
        __syncthreads();

        #pragma unroll
        for (int kk = 0; kk < BKT; kk++) {
            float a0 = As[kk][ty * 4 + 0];
            float a1 = As[kk][ty * 4 + 1];
            float a2 = As[kk][ty * 4 + 2];
            float a3 = As[kk][ty * 4 + 3];
            float4 bv = *(const float4*)&Bs[kk][tx * 4];
            acc[0][0] += a0 * bv.x; acc[0][1] += a0 * bv.y; acc[0][2] += a0 * bv.z; acc[0][3] += a0 * bv.w;
            acc[1][0] += a1 * bv.x; acc[1][1] += a1 * bv.y; acc[1][2] += a1 * bv.z; acc[1][3] += a1 * bv.w;
            acc[2][0] += a2 * bv.x; acc[2][1] += a2 * bv.y; acc[2][2] += a2 * bv.z; acc[2][3] += a2 * bv.w;
            acc[3][0] += a3 * bv.x; acc[3][1] += a3 * bv.y; acc[3][2] += a3 * bv.z; acc[3][3] += a3 * bv.w;
        }
        __syncthreads();
    }

    float* P = g_part + (size_t)ks * (B_ * H_);
    #pragma unroll
    for (int i = 0; i < 4; i++) {
        int r = row0 + ty * 4 + i;
        float4 v = make_float4(acc[i][0], acc[i][1], acc[i][2], acc[i][3]);
        *(float4*)&P[(size_t)r * H_ + col0 + tx * 4] = v;
    }
}

// ---------------------------------------------------------------------------
// Kernel 3: combine partials + bias + relu, then GEMM2 [1,768]@[768,42] + b2
//   one block per batch row
// ---------------------------------------------------------------------------
__global__ __launch_bounds__(256) void gemm2_kernel(
    const float* __restrict__ b1,
    const float* __restrict__ W2,   // [768, 42]
    const float* __restrict__ b2,
    float*       __restrict__ out)  // [256, 42]
{
    __shared__ float hs[H_];
    int b = blockIdx.x;
    int t = threadIdx.x;

    #pragma unroll
    for (int j = t; j < H_; j += 256) {
        float s = g_part[(size_t)0 * B_ * H_ + (size_t)b * H_ + j]
                + g_part[(size_t)1 * B_ * H_ + (size_t)b * H_ + j]
                + g_part[(size_t)2 * B_ * H_ + (size_t)b * H_ + j]
                + b1[j];
        hs[j] = fmaxf(s, 0.0f);
    }
    __syncthreads();

    int w    = t >> 5;
    int lane = t & 31;

    for (int n = w; n < NLAB; n += 8) {
        float s = 0.0f;
        #pragma unroll
        for (int k = lane; k < H_; k += 32) {
            s += hs[k] * W2[(size_t)k * NLAB + n];
        }
        #pragma unroll
        for (int off = 16; off > 0; off >>= 1)
            s += __shfl_down_sync(0xFFFFFFFFu, s, off);
        if (lane == 0)
            out[(size_t)b * NLAB + n] = s + b2[n];
    }
}

// ---------------------------------------------------------------------------
extern "C" void kernel_launch(void* const* d_in, const int* in_sizes, int n_in,
                              void* d_out, int out_size)
{
    const float* seq   = (const float*)d_in[0];   // [256,512,768]
    const int*   e1p   = (const int*)  d_in[1];
    const int*   e2p   = (const int*)  d_in[2];
    const int*   l1    = (const int*)  d_in[3];
    const int*   l2    = (const int*)  d_in[4];
    const float* wemb  = (const float*)d_in[5];   // [11,25]
    const float* W1    = (const float*)d_in[6];   // [2354,768]
    const float* b1    = (const float*)d_in[7];   // [768]
    const float* W2    = (const float*)d_in[8];   // [768,42]
    const float* b2    = (const float*)d_in[9];   // [42]
    float* out = (float*)d_out;

    build_combined_kernel<<<B_, 256>>>(seq, e1p, e2p, l1, l2, wemb);
    gemm1_kernel<<<dim3(H_ / BN, B_ / BM, KSPLIT), 256>>>(W1);
    gemm2_kernel<<<B_, 256>>>(b1, W2, b2, out);
}

// round 2
// speedup vs baseline: 2.0155x; 2.0155x over previous
#include <cuda_runtime.h>
#include <cuda_bf16.h>

// Problem constants
#define B_   256
#define S_   512
#define H_   768
#define WDIM 25
#define NLAB 42
#define CIN  2354   // 2*H + 2*WDIM + H
#define CINP 2356   // padded stride for g_comb (16B-aligned rows)
#define MAXW 10

// GEMM1 tiling
#define BM 64
#define BN 64
#define BKT 32
#define KSPLIT 3

// split-K boundaries, multiples of 4 for alignment
__device__ __constant__ int K0S[KSPLIT + 1] = {0, 788, 1576, CIN};

// Scratch (no cudaMalloc allowed)
__device__ float g_comb[B_ * CINP];                // [256, 2356] padded
__device__ float g_part[KSPLIT * B_ * H_];         // split-K partials [3, 256, 768]

// ---------------------------------------------------------------------------
// Kernel 1: build combined feature vector
//   combined = [e1_repr(768) | e2_repr(768) | e1_w(25) | e2_w(25) | ctx(768)]
// grid = (6 h-chunks, 256 batches), block = 256 (8 warps)
// warps split span positions, lanes split 128 h-cols (float4 each)
// ---------------------------------------------------------------------------
__global__ __launch_bounds__(256) void build_combined_kernel(
    const float* __restrict__ seq,      // [B,S,H]
    const int*   __restrict__ e1p,
    const int*   __restrict__ e2p,
    const int*   __restrict__ l1,
    const int*   __restrict__ l2,
    const float* __restrict__ wemb)     // [11, 25]
{
    const int b  = blockIdx.y;
    const int c  = blockIdx.x;          // h-chunk 0..5
    const int h0 = c * 128;
    const int t  = threadIdx.x;
    const int w    = t >> 5;
    const int lane = t & 31;

    const int p1 = e1p[b];
    const int p2 = e2p[b];

    const float* base = seq + (size_t)b * S_ * H_;
    float* out = g_comb + (size_t)b * CINP;

    // --- entity token reps (128 cols of each) ---
    if (t < 128) {
        out[h0 + t] = base[(size_t)p1 * H_ + h0 + t];
    } else {
        int tt = t - 128;
        out[H_ + h0 + tt] = base[(size_t)p2 * H_ + h0 + tt];
    }

    // --- width embeddings (chunk 0 only) ---
    if (c == 0) {
        if (t < WDIM) {
            int w1 = min(l1[b], MAXW);
            out[2 * H_ + t] = wemb[w1 * WDIM + t];
        } else if (t >= 32 && t < 32 + WDIM) {
            int w2 = min(l2[b], MAXW);
            out[2 * H_ + WDIM + (t - 32)] = wemb[w2 * WDIM + (t - 32)];
        }
    }

    // --- masked mean over positions strictly between p1 and p2 ---
    const int start = p1 + 1;
    const int end   = p2;               // exclusive
    const int cnt   = end - start;
    const float inv = (cnt > 0) ? (1.0f / (float)cnt) : 0.0f;

    float4 acc = make_float4(0.f, 0.f, 0.f, 0.f);
    for (int p = start + w; p < end; p += 8) {
        const float4* r = (const float4*)(base + (size_t)p * H_ + h0);
        float4 v = r[lane];
        acc.x += v.x; acc.y += v.y; acc.z += v.z; acc.w += v.w;
    }

    __shared__ float4 red[8][32];
    red[w][lane] = acc;
    __syncthreads();

    if (t < 32) {
        float4 s = red[0][t];
        #pragma unroll
        for (int i = 1; i < 8; i++) {
            float4 v = red[i][t];
            s.x += v.x; s.y += v.y; s.z += v.z; s.w += v.w;
        }
        int o = 2 * H_ + 2 * WDIM + h0 + t * 4;   // not 16B aligned -> scalar stores
        out[o + 0] = s.x * inv;
        out[o + 1] = s.y * inv;
        out[o + 2] = s.z * inv;
        out[o + 3] = s.w * inv;
    }
}

// ---------------------------------------------------------------------------
// Kernel 2: split-K GEMM1 partials with register prefetch double-buffering
//   M=256, N=768, K=2354. grid = (12, 4, 3), block = 256. 64x64 tile, 4x4 micro.
// ---------------------------------------------------------------------------
__global__ __launch_bounds__(256, 1) void gemm1_kernel(
    const float* __restrict__ W1)   // [CIN, H]
{
    __shared__ float As[BKT][BM + 4];   // transposed A tile, stride 68 (16B-aligned rows)
    __shared__ float Bs[BKT][BN];

    const int tid = threadIdx.x;
    const int bn = blockIdx.x;     // 0..11
    const int bm = blockIdx.y;     // 0..3
    const int ks = blockIdx.z;     // 0..2

    const int row0 = bm * BM;
    const int col0 = bn * BN;
    const int k0 = K0S[ks];
    const int k1 = K0S[ks + 1];

    const int ty = tid >> 4;       // 0..15 -> rows ty*4 .. ty*4+3
    const int tx = tid & 15;       // 0..15 -> cols tx*4 .. tx*4+3

    float acc[4][4] = {};
    float regA[8], regB[8];

    const float* A = g_comb;

    // prefetch first tile into registers
    #pragma unroll
    for (int i = 0; i < 8; i++) {
        int e  = tid + i * 256;
        int kg = k0 + (e & 31);
        regA[i] = (kg < k1) ? A[(size_t)(row0 + (e >> 5)) * CINP + kg] : 0.0f;
    }
    #pragma unroll
    for (int i = 0; i < 8; i++) {
        int e  = tid + i * 256;
        int kg = k0 + (e >> 6);
        regB[i] = (kg < k1) ? W1[(size_t)kg * H_ + col0 + (e & 63)] : 0.0f;
    }

    for (int kt = k0; kt < k1; kt += BKT) {
        // commit prefetched regs to smem
        #pragma unroll
        for (int i = 0; i < 8; i++) {
            int e = tid + i * 256;
            As[e & 31][e >> 5] = regA[i];
        }
        #pragma unroll
        for (int i = 0; i < 8; i++) {
            int e = tid + i * 256;
            Bs[e >> 6][e & 63] = regB[i];
        }
        __syncthreads();

        // prefetch next tile (overlaps with compute below)
        int ktn = kt + BKT;
        if (ktn < k1) {
            #pragma unroll
            for (int i = 0; i < 8; i++) {
                int e  = tid + i * 256;
                int kg = ktn + (e & 31);
                regA[i] = (kg < k1) ? A[(size_t)(row0 + (e >> 5)) * CINP + kg] : 0.0f;
            }
            #pragma unroll
            for (int i = 0; i < 8; i++) {
                int e  = tid + i * 256;
                int kg = ktn + (e >> 6);
                regB[i] = (kg < k1) ? W1[(size_t)kg * H_ + col0 + (e & 63)] : 0.0f;
            }
        }

        #pragma unroll
        for (int kk = 0; kk < BKT; kk++) {
            float4 av = *(const float4*)&As[kk][ty * 4];
            float4 bv = *(const float4*)&Bs[kk][tx * 4];
            acc[0][0] += av.x * bv.x; acc[0][1] += av.x * bv.y; acc[0][2] += av.x * bv.z; acc[0][3] += av.x * bv.w;
            acc[1][0] += av.y * bv.x; acc[1][1] += av.y * bv.y; acc[1][2] += av.y * bv.z; acc[1][3] += av.y * bv.w;
            acc[2][0] += av.z * bv.x; acc[2][1] += av.z * bv.y; acc[2][2] += av.z * bv.z; acc[2][3] += av.z * bv.w;
            acc[3][0] += av.w * bv.x; acc[3][1] += av.w * bv.y; acc[3][2] += av.w * bv.z; acc[3][3] += av.w * bv.w;
        }
        __syncthreads();
    }

    float* P = g_part + (size_t)ks * (B_ * H_);
    #pragma unroll
    for (int i = 0; i < 4; i++) {
        int r = row0 + ty * 4 + i;
        float4 v = make_float4(acc[i][0], acc[i][1], acc[i][2], acc[i][3]);
        *(float4*)&P[(size_t)r * H_ + col0 + tx * 4] = v;
    }
}

// ---------------------------------------------------------------------------
// Kernel 3: combine partials + bias + relu, then GEMM2 [1,768]@[768,42] + b2
// ---------------------------------------------------------------------------
__global__ __launch_bounds__(256) void gemm2_kernel(
    const float* __restrict__ b1,
    const float* __restrict__ W2,   // [768, 42]
    const float* __restrict__ b2,
    float*       __restrict__ out)  // [256, 42]
{
    __shared__ float hs[H_];
    int b = blockIdx.x;
    int t = threadIdx.x;

    #pragma unroll
    for (int j = t; j < H_; j += 256) {
        float s = g_part[(size_t)b * H_ + j]
                + g_part[(size_t)(B_ * H_) + (size_t)b * H_ + j]
                + g_part[(size_t)(2 * B_ * H_) + (size_t)b * H_ + j]
                + b1[j];
        hs[j] = fmaxf(s, 0.0f);
    }
    __syncthreads();

    int w    = t >> 5;
    int lane = t & 31;

    for (int n = w; n < NLAB; n += 8) {
        float s = 0.0f;
        #pragma unroll
        for (int k = lane; k < H_; k += 32) {
            s += hs[k] * W2[(size_t)k * NLAB + n];
        }
        #pragma unroll
        for (int off = 16; off > 0; off >>= 1)
            s += __shfl_down_sync(0xFFFFFFFFu, s, off);
        if (lane == 0)
            out[(size_t)b * NLAB + n] = s + b2[n];
    }
}

// ---------------------------------------------------------------------------
extern "C" void kernel_launch(void* const* d_in, const int* in_sizes, int n_in,
                              void* d_out, int out_size)
{
    const float* seq   = (const float*)d_in[0];   // [256,512,768]
    const int*   e1p   = (const int*)  d_in[1];
    const int*   e2p   = (const int*)  d_in[2];
    const int*   l1    = (const int*)  d_in[3];
    const int*   l2    = (const int*)  d_in[4];
    const float* wemb  = (const float*)d_in[5];   // [11,25]
    const float* W1    = (const float*)d_in[6];   // [2354,768]
    const float* b1    = (const float*)d_in[7];   // [768]
    const float* W2    = (const float*)d_in[8];   // [768,42]
    const float* b2    = (const float*)d_in[9];   // [42]
    float* out = (float*)d_out;

    build_combined_kernel<<<dim3(6, B_), 256>>>(seq, e1p, e2p, l1, l2, wemb);
    gemm1_kernel<<<dim3(H_ / BN, B_ / BM, KSPLIT), 256>>>(W1);
    gemm2_kernel<<<B_, 256>>>(b1, W2, b2, out);
}

// round 3
// speedup vs baseline: 2.1435x; 1.0635x over previous
#include <cuda_runtime.h>
#include <cuda_bf16.h>

typedef unsigned long long u64;

// Problem constants
#define B_   256
#define S_   512
#define H_   768
#define WDIM 25
#define NLAB 42
#define CIN  2354   // 2*H + 2*WDIM + H
#define CINP 2356   // padded stride for g_comb (16B-aligned rows, pad stays zero)
#define MAXW 10

// GEMM1 tiling: 128x128 block tile, 8x8 micro, split-K = 12
#define BM 128
#define BN 128
#define BKT 32
#define KSPLIT 12
#define KCH 196     // first 11 chunks; last chunk = 198 (ends at 2354)

// Scratch (no cudaMalloc allowed). Zero-initialized at load; pad cols never written.
__device__ float g_comb[B_ * CINP];                // [256, 2356]
__device__ float g_part[KSPLIT * B_ * H_];         // split-K partials [12, 256, 768]

// ---------------------------------------------------------------------------
// packed f32x2 helpers (sm_100+ PTX)
// ---------------------------------------------------------------------------
__device__ __forceinline__ u64 pack2(float x, float y) {
    u64 r;
    asm("mov.b64 %0, {%1, %2};" : "=l"(r) : "f"(x), "f"(y));
    return r;
}
__device__ __forceinline__ void unpack2(u64 v, float& x, float& y) {
    asm("mov.b64 {%0, %1}, %2;" : "=f"(x), "=f"(y) : "l"(v));
}
__device__ __forceinline__ void ffma2(u64& d, u64 a, u64 b) {
    asm("fma.rn.f32x2 %0, %1, %2, %0;" : "+l"(d) : "l"(a), "l"(b));
}

// ---------------------------------------------------------------------------
// Kernel 1: build combined feature vector
//   combined = [e1_repr(768) | e2_repr(768) | e1_w(25) | e2_w(25) | ctx(768)]
// grid = (6 h-chunks, 256 batches), block = 256 (8 warps)
// ---------------------------------------------------------------------------
__global__ __launch_bounds__(256) void build_combined_kernel(
    const float* __restrict__ seq,      // [B,S,H]
    const int*   __restrict__ e1p,
    const int*   __restrict__ e2p,
    const int*   __restrict__ l1,
    const int*   __restrict__ l2,
    const float* __restrict__ wemb)     // [11, 25]
{
    const int b  = blockIdx.y;
    const int c  = blockIdx.x;          // h-chunk 0..5
    const int h0 = c * 128;
    const int t  = threadIdx.x;
    const int w    = t >> 5;
    const int lane = t & 31;

    const int p1 = e1p[b];
    const int p2 = e2p[b];

    const float* base = seq + (size_t)b * S_ * H_;
    float* out = g_comb + (size_t)b * CINP;

    // --- entity token reps (128 cols of each) ---
    if (t < 128) {
        out[h0 + t] = base[(size_t)p1 * H_ + h0 + t];
    } else {
        int tt = t - 128;
        out[H_ + h0 + tt] = base[(size_t)p2 * H_ + h0 + tt];
    }

    // --- width embeddings (chunk 0 only) ---
    if (c == 0) {
        if (t < WDIM) {
            int w1 = min(l1[b], MAXW);
            out[2 * H_ + t] = wemb[w1 * WDIM + t];
        } else if (t >= 32 && t < 32 + WDIM) {
            int w2 = min(l2[b], MAXW);
            out[2 * H_ + WDIM + (t - 32)] = wemb[w2 * WDIM + (t - 32)];
        }
    }

    // --- masked mean over positions strictly between p1 and p2 ---
    const int start = p1 + 1;
    const int end   = p2;               // exclusive
    const int cnt   = end - start;
    const float inv = (cnt > 0) ? (1.0f / (float)cnt) : 0.0f;

    float4 acc0 = make_float4(0.f, 0.f, 0.f, 0.f);
    float4 acc1 = make_float4(0.f, 0.f, 0.f, 0.f);
    int p = start + w;
    for (; p + 8 < end; p += 16) {
        float4 v0 = ((const float4*)(base + (size_t)p * H_ + h0))[lane];
        float4 v1 = ((const float4*)(base + (size_t)(p + 8) * H_ + h0))[lane];
        acc0.x += v0.x; acc0.y += v0.y; acc0.z += v0.z; acc0.w += v0.w;
        acc1.x += v1.x; acc1.y += v1.y; acc1.z += v1.z; acc1.w += v1.w;
    }
    if (p < end) {
        float4 v0 = ((const float4*)(base + (size_t)p * H_ + h0))[lane];
        acc0.x += v0.x; acc0.y += v0.y; acc0.z += v0.z; acc0.w += v0.w;
    }
    acc0.x += acc1.x; acc0.y += acc1.y; acc0.z += acc1.z; acc0.w += acc1.w;

    __shared__ float4 red[8][32];
    red[w][lane] = acc0;
    __syncthreads();

    if (t < 32) {
        float4 s = red[0][t];
        #pragma unroll
        for (int i = 1; i < 8; i++) {
            float4 v = red[i][t];
            s.x += v.x; s.y += v.y; s.z += v.z; s.w += v.w;
        }
        int o = 2 * H_ + 2 * WDIM + h0 + t * 4;   // not 16B aligned -> scalar stores
        out[o + 0] = s.x * inv;
        out[o + 1] = s.y * inv;
        out[o + 2] = s.z * inv;
        out[o + 3] = s.w * inv;
    }
}

// ---------------------------------------------------------------------------
// Kernel 2: split-K GEMM1 partials:  part[ks] = comb[:, k0:k1] @ W1[k0:k1, :]
//   M=256, N=768, K=2354. grid = (6, 2, 12), block = 256.
//   128x128 tile, 8x8 micro, packed f32x2 FFMA, register-prefetch double buffer
// ---------------------------------------------------------------------------
__global__ __launch_bounds__(256, 1) void gemm1_kernel(
    const float* __restrict__ W1)   // [CIN, H]
{
    __shared__ float As[BKT][BM + 4];   // transposed A tile [k][m], stride 132
    __shared__ float Bs[BKT][BN];       // B tile [k][n]

    const int tid = threadIdx.x;
    const int bn = blockIdx.x;     // 0..5
    const int bm = blockIdx.y;     // 0..1
    const int ks = blockIdx.z;     // 0..11

    const int row0 = bm * BM;
    const int col0 = bn * BN;
    const int k0 = ks * KCH;
    const int k1 = (ks == KSPLIT - 1) ? CIN : (k0 + KCH);

    const int ty = tid >> 4;       // 0..15 -> rows ty*8 .. ty*8+7
    const int tx = tid & 15;       // 0..15 -> cols tx*8 .. tx*8+7

    // A-load mapping: 2 threads per row, 16 k each (4 float4)
    const int rA = tid >> 1;           // 0..127
    const int kh = (tid & 1) * 16;     // 0 or 16
    // B-load mapping: 8 threads per row, 16 n each (4 float4, coalesced)
    const int rB = tid >> 3;           // 0..31
    const int fB = tid & 7;            // float4 lane within row

    u64 acc[8][4] = {};
    float4 regA[4], regB[4];

    // ---- prefetch first tile ----
    {
        int kt = k0;
        #pragma unroll
        for (int i = 0; i < 4; i++) {
            int kg = kt + kh + 4 * i;
            regA[i] = (kg < k1) ? *(const float4*)&g_comb[(size_t)(row0 + rA) * CINP + kg]
                                : make_float4(0.f, 0.f, 0.f, 0.f);
        }
        #pragma unroll
        for (int i = 0; i < 4; i++) {
            int kg = kt + rB;
            int cc = col0 + (fB + 8 * i) * 4;
            regB[i] = (kg < k1) ? *(const float4*)&W1[(size_t)kg * H_ + cc]
                                : make_float4(0.f, 0.f, 0.f, 0.f);
        }
    }

    for (int kt = k0; kt < k1; kt += BKT) {
        // ---- commit prefetched regs to smem ----
        #pragma unroll
        for (int i = 0; i < 4; i++) {
            As[kh + 4 * i + 0][rA] = regA[i].x;
            As[kh + 4 * i + 1][rA] = regA[i].y;
            As[kh + 4 * i + 2][rA] = regA[i].z;
            As[kh + 4 * i + 3][rA] = regA[i].w;
        }
        #pragma unroll
        for (int i = 0; i < 4; i++) {
            *(float4*)&Bs[rB][(fB + 8 * i) * 4] = regB[i];
        }
        __syncthreads();

        // ---- prefetch next tile (overlaps with compute) ----
        int ktn = kt + BKT;
        if (ktn < k1) {
            #pragma unroll
            for (int i = 0; i < 4; i++) {
                int kg = ktn + kh + 4 * i;
                regA[i] = (kg < k1) ? *(const float4*)&g_comb[(size_t)(row0 + rA) * CINP + kg]
                                    : make_float4(0.f, 0.f, 0.f, 0.f);
            }
            #pragma unroll
            for (int i = 0; i < 4; i++) {
                int kg = ktn + rB;
                int cc = col0 + (fB + 8 * i) * 4;
                regB[i] = (kg < k1) ? *(const float4*)&W1[(size_t)kg * H_ + cc]
                                    : make_float4(0.f, 0.f, 0.f, 0.f);
            }
        }

        // ---- compute ----
        #pragma unroll 8
        for (int kk = 0; kk < BKT; kk++) {
            float4 a0 = *(const float4*)&As[kk][ty * 8];
            float4 a1 = *(const float4*)&As[kk][ty * 8 + 4];
            float4 b0 = *(const float4*)&Bs[kk][tx * 8];
            float4 b1 = *(const float4*)&Bs[kk][tx * 8 + 4];

            u64 bp0 = pack2(b0.x, b0.y);
            u64 bp1 = pack2(b0.z, b0.w);
            u64 bp2 = pack2(b1.x, b1.y);
            u64 bp3 = pack2(b1.z, b1.w);

            float av[8] = {a0.x, a0.y, a0.z, a0.w, a1.x, a1.y, a1.z, a1.w};
            #pragma unroll
            for (int i = 0; i < 8; i++) {
                u64 ap = pack2(av[i], av[i]);
                ffma2(acc[i][0], ap, bp0);
                ffma2(acc[i][1], ap, bp1);
                ffma2(acc[i][2], ap, bp2);
                ffma2(acc[i][3], ap, bp3);
            }
        }
        __syncthreads();
    }

    // ---- epilogue: write 8x8 micro-tile ----
    float* P = g_part + (size_t)ks * (B_ * H_);
    #pragma unroll
    for (int i = 0; i < 8; i++) {
        int r = row0 + ty * 8 + i;
        float4 v0, v1;
        unpack2(acc[i][0], v0.x, v0.y);
        unpack2(acc[i][1], v0.z, v0.w);
        unpack2(acc[i][2], v1.x, v1.y);
        unpack2(acc[i][3], v1.z, v1.w);
        *(float4*)&P[(size_t)r * H_ + col0 + tx * 8]     = v0;
        *(float4*)&P[(size_t)r * H_ + col0 + tx * 8 + 4] = v1;
    }
}

// ---------------------------------------------------------------------------
// Kernel 3: combine 12 partials + bias + relu, then GEMM2 [1,768]@[768,42] + b2
// ---------------------------------------------------------------------------
__global__ __launch_bounds__(256) void gemm2_kernel(
    const float* __restrict__ b1,
    const float* __restrict__ W2,   // [768, 42]
    const float* __restrict__ b2,
    float*       __restrict__ out)  // [256, 42]
{
    __shared__ float hs[H_];
    int b = blockIdx.x;
    int t = threadIdx.x;

    #pragma unroll
    for (int j = t; j < H_; j += 256) {
        float s = b1[j];
        #pragma unroll
        for (int ks = 0; ks < KSPLIT; ks++) {
            s += g_part[(size_t)ks * (B_ * H_) + (size_t)b * H_ + j];
        }
        hs[j] = fmaxf(s, 0.0f);
    }
    __syncthreads();

    int w    = t >> 5;
    int lane = t & 31;

    for (int n = w; n < NLAB; n += 8) {
        float s = 0.0f;
        #pragma unroll
        for (int k = lane; k < H_; k += 32) {
            s += hs[k] * W2[(size_t)k * NLAB + n];
        }
        #pragma unroll
        for (int off = 16; off > 0; off >>= 1)
            s += __shfl_down_sync(0xFFFFFFFFu, s, off);
        if (lane == 0)
            out[(size_t)b * NLAB + n] = s + b2[n];
    }
}

// ---------------------------------------------------------------------------
extern "C" void kernel_launch(void* const* d_in, const int* in_sizes, int n_in,
                              void* d_out, int out_size)
{
    const float* seq   = (const float*)d_in[0];   // [256,512,768]
    const int*   e1p   = (const int*)  d_in[1];
    const int*   e2p   = (const int*)  d_in[2];
    const int*   l1    = (const int*)  d_in[3];
    const int*   l2    = (const int*)  d_in[4];
    const float* wemb  = (const float*)d_in[5];   // [11,25]
    const float* W1    = (const float*)d_in[6];   // [2354,768]
    const float* b1    = (const float*)d_in[7];   // [768]
    const float* W2    = (const float*)d_in[8];   // [768,42]
    const float* b2    = (const float*)d_in[9];   // [42]
    float* out = (float*)d_out;

    build_combined_kernel<<<dim3(6, B_), 256>>>(seq, e1p, e2p, l1, l2, wemb);
    gemm1_kernel<<<dim3(H_ / BN, B_ / BM, KSPLIT), 256>>>(W1);
    gemm2_kernel<<<B_, 256>>>(b1, W2, b2, out);
}